// round 9
// baseline (speedup 1.0000x reference)
#include <cuda_runtime.h>
#include <math_constants.h>

// ChamferLoss B=8, N=8192, D=3 — R9: fused both directions (R7 structure),
// but all packed-register half accesses via union bit-cast (zero-cost register
// pair aliasing) instead of asm mov.b64 unpacks. Inner unit (2 preds x 1 gt):
// 3 fma2 + 1 add2 + 4 scalar FMNMX, no MOVs.

#define NPTS   8192
#define BATCH  8
#define TPB    128
#define RP     8                          // pred pairs per lane (16 preds)
#define REFS_PER_BLOCK (TPB * RP * 2)     // 2048
#define PT     (NPTS / REFS_PER_BLOCK)    // 4 pred tiles
#define QS     16                         // gt slices
#define QPER   (NPTS / QS)                // 512 gts per block
#define QB     8                          // gt batch (fold granularity)
#define NWARP  (TPB / 32)                 // 4
#define FLATN  (BATCH * NPTS)             // 65536

__device__ float g_row[PT * NWARP][FLATN];   // 16 slices of per-gt row mins
__device__ float g_col[QS][FLATN];           // 16 slices of per-pred col mins

typedef unsigned long long ull;

union P2 {
    ull    u;
    float2 f;
};

struct __align__(16) QPack { ull x, y, z, n; };

__device__ __forceinline__ ull pack2(float a, float b) {
    P2 p; p.f = make_float2(a, b); return p.u;
}
__device__ __forceinline__ ull fma2(ull a, ull b, ull c) {
    ull r; asm("fma.rn.f32x2 %0, %1, %2, %3;" : "=l"(r) : "l"(a), "l"(b), "l"(c)); return r;
}
__device__ __forceinline__ ull add2(ull a, ull b) {
    ull r; asm("add.rn.f32x2 %0, %1, %2;" : "=l"(r) : "l"(a), "l"(b)); return r;
}

__global__ __launch_bounds__(TPB, 4)
void chamfer_fused_kernel(const float* __restrict__ preds,
                          const float* __restrict__ gts,
                          float* __restrict__ out) {
    __shared__ QPack qbuf[QPER];   // 16KB

    if (blockIdx.x == 0 && blockIdx.y == 0 && blockIdx.z == 0 &&
        threadIdx.x == 0) {
        out[0] = 0.0f;   // only the later reduce kernel touches out
    }

    const int pt  = blockIdx.x;
    const int b   = blockIdx.y;
    const int s   = blockIdx.z;
    const int tid = threadIdx.x;
    const int w   = tid >> 5;
    const int L   = tid & 31;

    // ---- this lane's 16 preds in registers (8 packed pairs) ----
    ull rx2[RP], ry2[RP], rz2[RP], rn2[RP];
    float colL[RP], colH[RP];
    const int refbase = pt * REFS_PER_BLOCK + w * (RP * 64) + L * 2;
    #pragma unroll
    for (int r = 0; r < RP; r++) {
        const int idx = refbase + r * 64;
        const float* rp = preds + ((size_t)b * NPTS + idx) * 3;
        const float2 v0 = *(const float2*)(rp + 0);
        const float2 v1 = *(const float2*)(rp + 2);
        const float2 v2 = *(const float2*)(rp + 4);
        rx2[r] = pack2(v0.x, v1.y);
        ry2[r] = pack2(v0.y, v2.x);
        rz2[r] = pack2(v1.x, v2.y);
        rn2[r] = pack2(v0.x * v0.x + v0.y * v0.y + v1.x * v1.x,
                       v1.y * v1.y + v2.x * v2.x + v2.y * v2.y);
        colL[r] = CUDART_INF_F;
        colH[r] = CUDART_INF_F;
    }

    // ---- stage gt slice in shared: duplicated, prescaled -2, packed norm ----
    for (int q = tid; q < QPER; q += TPB) {
        const float* gp = gts + ((size_t)b * NPTS + s * QPER + q) * 3;
        const float gx = gp[0], gy = gp[1], gz = gp[2];
        QPack pk;
        pk.x = pack2(-2.0f * gx, -2.0f * gx);
        pk.y = pack2(-2.0f * gy, -2.0f * gy);
        pk.z = pack2(-2.0f * gz, -2.0f * gz);
        const float gn = gx * gx + gy * gy + gz * gz;
        pk.n = pack2(gn, gn);
        qbuf[q] = pk;
    }
    __syncthreads();

    float* growp = &g_row[pt * NWARP + w][(size_t)b * NPTS + s * QPER];

    for (int qb = 0; qb < QPER; qb += QB) {
        float rowloc[QB];
        #pragma unroll
        for (int qq = 0; qq < QB; qq++) {
            const ulonglong2 pxy = *(const ulonglong2*)(&qbuf[qb + qq].x);
            const ulonglong2 pzn = *(const ulonglong2*)(&qbuf[qb + qq].z);
            float ra = CUDART_INF_F, rb = CUDART_INF_F;
            #pragma unroll
            for (int r = 0; r < RP; r++) {
                P2 t;
                t.u = fma2(pzn.x, rz2[r], rn2[r]);
                t.u = fma2(pxy.y, ry2[r], t.u);
                t.u = fma2(pxy.x, rx2[r], t.u);    // ||p||^2 - 2<g,p>, 2 preds
                ra = fminf(ra, t.f.x);             // row-min (halves read free)
                rb = fminf(rb, t.f.y);
                P2 u;
                u.u = add2(t.u, pzn.y);            // + ||g||^2 -> full distance
                colL[r] = fminf(colL[r], u.f.x);
                colH[r] = fminf(colH[r], u.f.y);
            }
            rowloc[qq] = fminf(ra, rb);
        }

        // ---- fold-shuffle: reduce 8 per-lane values across 32 lanes ----
        #pragma unroll
        for (int k = 0; k < 4; k++) {
            const float sent = (L & 16) ? rowloc[k] : rowloc[k + 4];
            const float recv = __shfl_xor_sync(0xffffffffu, sent, 16);
            const float keep = (L & 16) ? rowloc[k + 4] : rowloc[k];
            rowloc[k] = fminf(keep, recv);
        }
        #pragma unroll
        for (int k = 0; k < 2; k++) {
            const float sent = (L & 8) ? rowloc[k] : rowloc[k + 2];
            const float recv = __shfl_xor_sync(0xffffffffu, sent, 8);
            const float keep = (L & 8) ? rowloc[k + 2] : rowloc[k];
            rowloc[k] = fminf(keep, recv);
        }
        {
            const float sent = (L & 4) ? rowloc[0] : rowloc[1];
            const float recv = __shfl_xor_sync(0xffffffffu, sent, 4);
            const float keep = (L & 4) ? rowloc[1] : rowloc[0];
            rowloc[0] = fminf(keep, recv);
        }
        rowloc[0] = fminf(rowloc[0], __shfl_xor_sync(0xffffffffu, rowloc[0], 2));
        rowloc[0] = fminf(rowloc[0], __shfl_xor_sync(0xffffffffu, rowloc[0], 1));

        const int qi = qb + (((L >> 4) & 1) << 2) + (((L >> 3) & 1) << 1) +
                       ((L >> 2) & 1);
        if ((L & 3) == 0) growp[qi] = rowloc[0];
    }

    // ---- write col-min partials for this gt slice ----
    #pragma unroll
    for (int r = 0; r < RP; r++) {
        const int idx = refbase + r * 64;
        float2 v; v.x = colL[r]; v.y = colH[r];
        *(float2*)(&g_col[s][(size_t)b * NPTS + idx]) = v;
    }
}

__global__ __launch_bounds__(256)
void chamfer_reduce_kernel(const float* __restrict__ gts,
                           float* __restrict__ out) {
    __shared__ float sred[256];
    const int idx = blockIdx.x * 256 + threadIdx.x;   // 0 .. 2*FLATN-1

    float v;
    if (idx < FLATN) {
        v = g_col[0][idx];
        #pragma unroll
        for (int s = 1; s < QS; s++) v = fminf(v, g_col[s][idx]);
    } else {
        const int g = idx - FLATN;
        v = g_row[0][g];
        #pragma unroll
        for (int k = 1; k < PT * NWARP; k++) v = fminf(v, g_row[k][g]);
        const float* gp = gts + (size_t)g * 3;
        v += gp[0] * gp[0] + gp[1] * gp[1] + gp[2] * gp[2];
    }

    sred[threadIdx.x] = v;
    __syncthreads();
    #pragma unroll
    for (int sft = 128; sft > 32; sft >>= 1) {
        if (threadIdx.x < sft) sred[threadIdx.x] += sred[threadIdx.x + sft];
        __syncthreads();
    }
    if (threadIdx.x < 32) {
        float r = sred[threadIdx.x] + sred[threadIdx.x + 32];
        #pragma unroll
        for (int o = 16; o > 0; o >>= 1)
            r += __shfl_down_sync(0xffffffffu, r, o);
        if (threadIdx.x == 0) atomicAdd(out, r);
    }
}

extern "C" void kernel_launch(void* const* d_in, const int* in_sizes, int n_in,
                              void* d_out, int out_size) {
    const float* preds = (const float*)d_in[0];
    const float* gts   = (const float*)d_in[1];
    float* out = (float*)d_out;

    dim3 grid(PT, BATCH, QS);   // (4, 8, 16) = 512 blocks, occ 4 -> one wave
    chamfer_fused_kernel<<<grid, TPB>>>(preds, gts, out);

    chamfer_reduce_kernel<<<(2 * FLATN) / 256, 256>>>(gts, out);
}

// round 10
// speedup vs baseline: 1.0831x; 1.0831x over previous
#include <cuda_runtime.h>
#include <math_constants.h>

// ChamferLoss B=8, N=8192, D=3 — R10: fused both directions; RP=4 (8 preds
// per lane) so occupancy 7 -> 7 warps/SMSP for latency hiding (was 4).
// Inner unit (2 preds x 1 gt): 3 fma2 + 1 add2 + 4 scalar FMNMX.

#define NPTS   8192
#define BATCH  8
#define TPB    128
#define RP     4                          // pred pairs per lane (8 preds)
#define REFS_PER_BLOCK (TPB * RP * 2)     // 1024
#define PT     (NPTS / REFS_PER_BLOCK)    // 8 pred tiles
#define QS     16                         // gt slices
#define QPER   (NPTS / QS)                // 512 gts per block
#define QB     8                          // gt batch (fold granularity)
#define NWARP  (TPB / 32)                 // 4
#define FLATN  (BATCH * NPTS)             // 65536

__device__ float g_row[PT * NWARP][FLATN];   // 32 slices of per-gt row mins
__device__ float g_col[QS][FLATN];           // 16 slices of per-pred col mins

typedef unsigned long long ull;

union P2 {
    ull    u;
    float2 f;
};

struct __align__(16) QPack { ull x, y, z, n; };

__device__ __forceinline__ ull pack2(float a, float b) {
    P2 p; p.f = make_float2(a, b); return p.u;
}
__device__ __forceinline__ ull fma2(ull a, ull b, ull c) {
    ull r; asm("fma.rn.f32x2 %0, %1, %2, %3;" : "=l"(r) : "l"(a), "l"(b), "l"(c)); return r;
}
__device__ __forceinline__ ull add2(ull a, ull b) {
    ull r; asm("add.rn.f32x2 %0, %1, %2;" : "=l"(r) : "l"(a), "l"(b)); return r;
}

__global__ __launch_bounds__(TPB, 7)
void chamfer_fused_kernel(const float* __restrict__ preds,
                          const float* __restrict__ gts,
                          float* __restrict__ out) {
    __shared__ QPack qbuf[QPER];   // 16KB

    if (blockIdx.x == 0 && blockIdx.y == 0 && blockIdx.z == 0 &&
        threadIdx.x == 0) {
        out[0] = 0.0f;   // only the later reduce kernel touches out
    }

    const int pt  = blockIdx.x;
    const int b   = blockIdx.y;
    const int s   = blockIdx.z;
    const int tid = threadIdx.x;
    const int w   = tid >> 5;
    const int L   = tid & 31;

    // ---- this lane's 8 preds in registers (4 packed pairs) ----
    ull rx2[RP], ry2[RP], rz2[RP], rn2[RP];
    float colL[RP], colH[RP];
    const int refbase = pt * REFS_PER_BLOCK + w * (RP * 64) + L * 2;
    #pragma unroll
    for (int r = 0; r < RP; r++) {
        const int idx = refbase + r * 64;
        const float* rp = preds + ((size_t)b * NPTS + idx) * 3;
        const float2 v0 = *(const float2*)(rp + 0);
        const float2 v1 = *(const float2*)(rp + 2);
        const float2 v2 = *(const float2*)(rp + 4);
        rx2[r] = pack2(v0.x, v1.y);
        ry2[r] = pack2(v0.y, v2.x);
        rz2[r] = pack2(v1.x, v2.y);
        rn2[r] = pack2(v0.x * v0.x + v0.y * v0.y + v1.x * v1.x,
                       v1.y * v1.y + v2.x * v2.x + v2.y * v2.y);
        colL[r] = CUDART_INF_F;
        colH[r] = CUDART_INF_F;
    }

    // ---- stage gt slice in shared: duplicated, prescaled -2, packed norm ----
    for (int q = tid; q < QPER; q += TPB) {
        const float* gp = gts + ((size_t)b * NPTS + s * QPER + q) * 3;
        const float gx = gp[0], gy = gp[1], gz = gp[2];
        QPack pk;
        pk.x = pack2(-2.0f * gx, -2.0f * gx);
        pk.y = pack2(-2.0f * gy, -2.0f * gy);
        pk.z = pack2(-2.0f * gz, -2.0f * gz);
        const float gn = gx * gx + gy * gy + gz * gz;
        pk.n = pack2(gn, gn);
        qbuf[q] = pk;
    }
    __syncthreads();

    float* growp = &g_row[pt * NWARP + w][(size_t)b * NPTS + s * QPER];

    for (int qb = 0; qb < QPER; qb += QB) {
        float rowloc[QB];
        #pragma unroll
        for (int qq = 0; qq < QB; qq++) {
            const ulonglong2 pxy = *(const ulonglong2*)(&qbuf[qb + qq].x);
            const ulonglong2 pzn = *(const ulonglong2*)(&qbuf[qb + qq].z);
            float ra = CUDART_INF_F, rb = CUDART_INF_F;
            #pragma unroll
            for (int r = 0; r < RP; r++) {
                P2 t;
                t.u = fma2(pzn.x, rz2[r], rn2[r]);
                t.u = fma2(pxy.y, ry2[r], t.u);
                t.u = fma2(pxy.x, rx2[r], t.u);    // ||p||^2 - 2<g,p>, 2 preds
                ra = fminf(ra, t.f.x);
                rb = fminf(rb, t.f.y);
                P2 u;
                u.u = add2(t.u, pzn.y);            // + ||g||^2 -> full distance
                colL[r] = fminf(colL[r], u.f.x);
                colH[r] = fminf(colH[r], u.f.y);
            }
            rowloc[qq] = fminf(ra, rb);
        }

        // ---- fold-shuffle: reduce 8 per-lane values across 32 lanes ----
        #pragma unroll
        for (int k = 0; k < 4; k++) {
            const float sent = (L & 16) ? rowloc[k] : rowloc[k + 4];
            const float recv = __shfl_xor_sync(0xffffffffu, sent, 16);
            const float keep = (L & 16) ? rowloc[k + 4] : rowloc[k];
            rowloc[k] = fminf(keep, recv);
        }
        #pragma unroll
        for (int k = 0; k < 2; k++) {
            const float sent = (L & 8) ? rowloc[k] : rowloc[k + 2];
            const float recv = __shfl_xor_sync(0xffffffffu, sent, 8);
            const float keep = (L & 8) ? rowloc[k + 2] : rowloc[k];
            rowloc[k] = fminf(keep, recv);
        }
        {
            const float sent = (L & 4) ? rowloc[0] : rowloc[1];
            const float recv = __shfl_xor_sync(0xffffffffu, sent, 4);
            const float keep = (L & 4) ? rowloc[1] : rowloc[0];
            rowloc[0] = fminf(keep, recv);
        }
        rowloc[0] = fminf(rowloc[0], __shfl_xor_sync(0xffffffffu, rowloc[0], 2));
        rowloc[0] = fminf(rowloc[0], __shfl_xor_sync(0xffffffffu, rowloc[0], 1));

        const int qi = qb + (((L >> 4) & 1) << 2) + (((L >> 3) & 1) << 1) +
                       ((L >> 2) & 1);
        if ((L & 3) == 0) growp[qi] = rowloc[0];
    }

    // ---- write col-min partials for this gt slice ----
    #pragma unroll
    for (int r = 0; r < RP; r++) {
        const int idx = refbase + r * 64;
        float2 v; v.x = colL[r]; v.y = colH[r];
        *(float2*)(&g_col[s][(size_t)b * NPTS + idx]) = v;
    }
}

__global__ __launch_bounds__(256)
void chamfer_reduce_kernel(const float* __restrict__ gts,
                           float* __restrict__ out) {
    __shared__ float sred[256];
    const int idx = blockIdx.x * 256 + threadIdx.x;   // 0 .. 2*FLATN-1

    float v;
    if (idx < FLATN) {
        v = g_col[0][idx];
        #pragma unroll
        for (int s = 1; s < QS; s++) v = fminf(v, g_col[s][idx]);
    } else {
        const int g = idx - FLATN;
        v = g_row[0][g];
        #pragma unroll
        for (int k = 1; k < PT * NWARP; k++) v = fminf(v, g_row[k][g]);
        const float* gp = gts + (size_t)g * 3;
        v += gp[0] * gp[0] + gp[1] * gp[1] + gp[2] * gp[2];
    }

    sred[threadIdx.x] = v;
    __syncthreads();
    #pragma unroll
    for (int sft = 128; sft > 32; sft >>= 1) {
        if (threadIdx.x < sft) sred[threadIdx.x] += sred[threadIdx.x + sft];
        __syncthreads();
    }
    if (threadIdx.x < 32) {
        float r = sred[threadIdx.x] + sred[threadIdx.x + 32];
        #pragma unroll
        for (int o = 16; o > 0; o >>= 1)
            r += __shfl_down_sync(0xffffffffu, r, o);
        if (threadIdx.x == 0) atomicAdd(out, r);
    }
}

extern "C" void kernel_launch(void* const* d_in, const int* in_sizes, int n_in,
                              void* d_out, int out_size) {
    const float* preds = (const float*)d_in[0];
    const float* gts   = (const float*)d_in[1];
    float* out = (float*)d_out;

    dim3 grid(PT, BATCH, QS);   // (8, 8, 16) = 1024 blocks, occ 7 -> one wave
    chamfer_fused_kernel<<<grid, TPB>>>(preds, gts, out);

    chamfer_reduce_kernel<<<(2 * FLATN) / 256, 256>>>(gts, out);
}